// round 12
// baseline (speedup 1.0000x reference)
#include <cuda_runtime.h>
#include <cuda_bf16.h>
#include <cuda_pipeline.h>

#define NN 4096
#define ITERS 8
#define SWEEPS 6
#define MV_BLOCKS 128
#define MV_TPB 512
#define NCHUNK 16
#define ROW_CB 512                      // bytes per row per chunk (256 bf16)
#define CHUNK_B (32 * ROW_CB)           // 16 KB per chunk stage

// dynamic smem layout for cg_kernel
#define OFF_ZS    0
#define OFF_RS    16384
#define OFF_APS   32768
#define OFF_MINV  49152
#define OFF_TSS   65536          // 64*33 floats = 8448 B
#define OFF_WRED  73984          // 16*3 floats = 192 B
#define OFF_SCL   74176          // 3 floats + pad -> 74240
#define OFF_STAGE 74240          // 3 x 16 KB
#define SMEM_CG   (OFF_STAGE + 3 * CHUNK_B)   // 123392 bytes

// ---------------- persistent device scratch (static, no runtime alloc) ----------------
__device__ __nv_bfloat16 g_D16[(size_t)NN * NN];   // lamda1 * D_tilda in bf16 (33.5 MB)
__device__ float g_qr[NN];        // q + rho
__device__ float g_Minv[NN];      // Jacobi preconditioner
__device__ float g_StS[64 * 64];  // lamda2 * S^T S
__device__ float g_x[NN], g_r[NN], g_z[NN], g_Az[NN];
__device__ int   g_barA[ITERS];

// ------- 0) convert + setup fused: g_D16 = bf16(lamda1*D); last block does setup -----
__global__ void __launch_bounds__(256) convert_kernel(
    const float* __restrict__ D, const float* __restrict__ l1p,
    const float* __restrict__ inp, const float* __restrict__ L,
    const void* __restrict__ maskv, const float* __restrict__ thP,
    const float* __restrict__ l2p, const float* __restrict__ rhop,
    const float* __restrict__ S)
{
    __shared__ float Ss[64 * 65];
    __shared__ float Ts[64 * 65];
    float l1 = *l1p;
    int t = threadIdx.x;

    // bulk convert (all blocks, including the setup block)
    size_t base = ((size_t)blockIdx.x * 256 + t) * 8;   // float4 index
    const float4* src = (const float4*)D;
    __nv_bfloat162* dst = (__nv_bfloat162*)g_D16;
    float4 v[8];
    #pragma unroll
    for (int i = 0; i < 8; i++) v[i] = src[base + i];
    #pragma unroll
    for (int i = 0; i < 8; i++) {
        __nv_bfloat162 lo, hi;
        lo.x = __float2bfloat16_rn(v[i].x * l1); lo.y = __float2bfloat16_rn(v[i].y * l1);
        hi.x = __float2bfloat16_rn(v[i].z * l1); hi.y = __float2bfloat16_rn(v[i].w * l1);
        dst[(base + i) * 2]     = lo;
        dst[(base + i) * 2 + 1] = hi;
    }

    if (blockIdx.x != 2047) return;

    // ---------------- setup (256 threads) ----------------
    float l2 = *l2p, rho = *rhop;

    // detect mask storage: 4-byte words (int32 0/1 or float 0.0/1.0) vs packed bytes
    const unsigned* maskw = (const unsigned*)maskv;
    unsigned wvd = maskw[t];   // first 256 words cover 1024 packed bools
    int bad = (wvd != 0u && wvd != 1u && wvd != 0x3F800000u) ? 1 : 0;
    int bytemode = __syncthreads_or(bad);

    for (int i = t; i < 4096; i += 256) {
        int h = i >> 6, a = i & 63;
        Ss[h * 65 + a] = S[i];
    }
    __syncthreads();
    for (int e = t; e < 4096; e += 256) {
        int a = e >> 6, b = e & 63;
        float acc = 0.f;
        #pragma unroll 8
        for (int h = 0; h < 64; h++) acc += Ss[h * 65 + a] * Ss[h * 65 + b];
        acc *= l2;
        Ts[a * 65 + b] = acc;
        g_StS[e] = acc;
    }
    __syncthreads();
    const unsigned char* maskb = (const unsigned char*)maskv;
    for (int n = t; n < NN; n += 256) {
        float qf;
        if (bytemode) qf = (maskb[n] != 0) ? 1.f : 0.f;
        else          qf = (maskw[n] != 0u) ? 1.f : 0.f;
        float qr = qf + rho;
        g_qr[n] = qr;
        int c = n & 63;
        float dg = D[(size_t)n * (NN + 1)];
        float denom = qr + l1 * dg + Ts[c * 65 + c];
        float minv = 1.f / denom;
        g_Minv[n] = minv;
        float bb = rho * (L[n] - thP[n]) + (qf != 0.f ? inp[n] : 0.f);
        g_r[n] = bb;
        g_z[n] = minv * bb;
    }
    if (t < ITERS) g_barA[t] = 0;
}

// ---------------- 2) PERSISTENT CG: one grid barrier per iteration -------------------
// Each block publishes its 32 Az values, then redundantly maintains the FULL r/z/Ap
// vectors in its own smem (identical op order in every block -> bitwise-identical
// alpha/beta everywhere; no global dot reduction, no atomics).
__global__ void __launch_bounds__(MV_TPB) cg_kernel()
{
    extern __shared__ __align__(16) char sm[];
    float* zs    = (float*)(sm + OFF_ZS);
    float* rs    = (float*)(sm + OFF_RS);
    float* Aps   = (float*)(sm + OFF_APS);
    float* Minvs = (float*)(sm + OFF_MINV);
    float* Tss   = (float*)(sm + OFF_TSS);
    float* wred  = (float*)(sm + OFF_WRED);
    float* scl   = (float*)(sm + OFF_SCL);
    __nv_bfloat16* stage = (__nv_bfloat16*)(sm + OFF_STAGE);

    int t = threadIdx.x, b = blockIdx.x;
    int row0 = b * 32;
    int h = row0 >> 6;
    int u0 = (b & 1) * 32;
    int warp = t >> 5, lane = t & 31;
    int r0 = row0 + 2 * warp;

    // init local full vectors + StS tile
    for (int i = t; i < NN; i += MV_TPB) {
        zs[i]  = __ldcg(&g_z[i]);
        rs[i]  = __ldcg(&g_r[i]);
        Minvs[i] = __ldcg(&g_Minv[i]);
        Aps[i] = 0.f;
    }
    for (int i = t; i < 64 * 32; i += MV_TPB) {
        int bb = i >> 5, uu = i & 31;
        Tss[bb * 33 + uu] = g_StS[bb * 64 + u0 + uu];
    }

    int lrow = t >> 4;
    int loff = (t & 15) * 32;
    const char* srow = (const char*)(g_D16 + (size_t)(row0 + lrow) * NN);

    float rz_prev = 0.f, pAp_prev = 0.f;
    float zr_save = 0.f, p_reg = 0.f, x_reg = 0.f;   // meaningful for lane<2 threads

    for (int k = 0; k < ITERS; k++) {
        // ---- matvec on local zs ----
        #pragma unroll
        for (int c = 0; c < 2; c++) {
            char* d = (char*)stage + (c % 3) * CHUNK_B + lrow * ROW_CB + loff;
            const char* s = srow + c * ROW_CB + loff;
            __pipeline_memcpy_async(d, s, 16);
            __pipeline_memcpy_async(d + 16, s + 16, 16);
            __pipeline_commit();
        }
        __syncthreads();   // zs/Aps/etc ready (also covers init on k=0)

        float acc0 = 0.f, acc1 = 0.f;
        #pragma unroll
        for (int c = 0; c < NCHUNK; c++) {
            if (c < NCHUNK - 1) __pipeline_wait_prior(1);
            else                __pipeline_wait_prior(0);
            __syncthreads();
            const char* st = (const char*)stage + (c % 3) * CHUNK_B;
            uint4 d0 = *(const uint4*)(st + (2 * warp) * ROW_CB + lane * 16);
            uint4 d1 = *(const uint4*)(st + (2 * warp + 1) * ROW_CB + lane * 16);
            float4 za = *(const float4*)(zs + c * 256 + lane * 8);
            float4 zb = *(const float4*)(zs + c * 256 + lane * 8 + 4);
            float2 p0 = __bfloat1622float2(*(__nv_bfloat162*)&d0.x);
            float2 p1 = __bfloat1622float2(*(__nv_bfloat162*)&d0.y);
            float2 p2 = __bfloat1622float2(*(__nv_bfloat162*)&d0.z);
            float2 p3 = __bfloat1622float2(*(__nv_bfloat162*)&d0.w);
            acc0 += p0.x * za.x + p0.y * za.y + p1.x * za.z + p1.y * za.w
                  + p2.x * zb.x + p2.y * zb.y + p3.x * zb.z + p3.y * zb.w;
            p0 = __bfloat1622float2(*(__nv_bfloat162*)&d1.x);
            p1 = __bfloat1622float2(*(__nv_bfloat162*)&d1.y);
            p2 = __bfloat1622float2(*(__nv_bfloat162*)&d1.z);
            p3 = __bfloat1622float2(*(__nv_bfloat162*)&d1.w);
            acc1 += p0.x * za.x + p0.y * za.y + p1.x * za.z + p1.y * za.w
                  + p2.x * zb.x + p2.y * zb.y + p3.x * zb.z + p3.y * zb.w;
            if (c + 2 < NCHUNK) {
                int cc = c + 2;
                char* d = (char*)stage + (cc % 3) * CHUNK_B + lrow * ROW_CB + loff;
                const char* s = srow + cc * ROW_CB + loff;
                __pipeline_memcpy_async(d, s, 16);
                __pipeline_memcpy_async(d + 16, s + 16, 16);
                __pipeline_commit();
            }
        }

        // lamda2 * (Z @ StS) term
        {
            int uu0 = (r0 & 63) - u0;
            int uu1 = uu0 + 1;
            float zl  = zs[(h << 6) + lane];
            float zh2 = zs[(h << 6) + lane + 32];
            acc0 += Tss[lane * 33 + uu0] * zl + Tss[(lane + 32) * 33 + uu0] * zh2;
            acc1 += Tss[lane * 33 + uu1] * zl + Tss[(lane + 32) * 33 + uu1] * zh2;
        }
        #pragma unroll
        for (int off = 16; off; off >>= 1) {
            acc0 += __shfl_xor_sync(0xffffffffu, acc0, off);
            acc1 += __shfl_xor_sync(0xffffffffu, acc1, off);
        }
        if (lane < 2) {
            int row = r0 + lane;
            float a = lane ? acc1 : acc0;
            zr_save = zs[row];
            float Azv = a + g_qr[row] * zr_save;
            g_Az[row] = Azv;          // publish own 32 Az values
            __threadfence();
        }
        __syncthreads();

        // ---- single grid barrier ----
        if (t == 0) {
            atomicAdd(&g_barA[k], 1);
            while (*(volatile int*)&g_barA[k] < MV_BLOCKS) __nanosleep(32);
        }
        __syncthreads();

        // ---- read full Az; local dots (identical in every block) ----
        float4 aza = __ldcg((const float4*)g_Az + 2 * t);
        float4 azb = __ldcg((const float4*)g_Az + 2 * t + 1);
        float az[8] = {aza.x, aza.y, aza.z, aza.w, azb.x, azb.y, azb.z, azb.w};
        float dzAz = 0.f, dzAp = 0.f, drz = 0.f;
        #pragma unroll
        for (int i = 0; i < 8; i++) {
            int n = t * 8 + i;
            float zn = zs[n];
            dzAz += zn * az[i];
            dzAp += zn * Aps[n];
            drz  += rs[n] * zn;
        }
        #pragma unroll
        for (int off = 16; off; off >>= 1) {
            dzAz += __shfl_xor_sync(0xffffffffu, dzAz, off);
            dzAp += __shfl_xor_sync(0xffffffffu, dzAp, off);
            drz  += __shfl_xor_sync(0xffffffffu, drz,  off);
        }
        if (lane == 0) {
            wred[warp * 3 + 0] = dzAz;
            wred[warp * 3 + 1] = dzAp;
            wred[warp * 3 + 2] = drz;
        }
        __syncthreads();
        if (warp == 0) {
            float a = (lane < 16) ? wred[lane * 3 + 0] : 0.f;
            float bq = (lane < 16) ? wred[lane * 3 + 1] : 0.f;
            float cc = (lane < 16) ? wred[lane * 3 + 2] : 0.f;
            #pragma unroll
            for (int off = 8; off; off >>= 1) {
                a  += __shfl_xor_sync(0xffffffffu, a,  off);
                bq += __shfl_xor_sync(0xffffffffu, bq, off);
                cc += __shfl_xor_sync(0xffffffffu, cc, off);
            }
            if (lane == 0) { scl[0] = a; scl[1] = bq; scl[2] = cc; }
        }
        __syncthreads();
        float zAz = scl[0], zAp = scl[1], rz = scl[2];
        float beta = (k > 0 && rz_prev != 0.f) ? rz / rz_prev : 0.f;
        float pAp = zAz + 2.f * beta * zAp + beta * beta * pAp_prev;
        float alpha = (pAp != 0.f) ? rz / pAp : 0.f;
        rz_prev = rz; pAp_prev = pAp;

        // own-row p/x (zr_save is z_k for this row, captured pre-update)
        if (lane < 2) {
            p_reg = zr_save + beta * p_reg;
            x_reg = x_reg + alpha * p_reg;
        }

        // ---- redundant full-vector update (8 rows/thread) ----
        #pragma unroll
        for (int i = 0; i < 8; i++) {
            int n = t * 8 + i;
            float Apn = az[i] + beta * Aps[n];
            Aps[n] = Apn;
            float rn = rs[n] - alpha * Apn;
            rs[n] = rn;
            zs[n] = Minvs[n] * rn;
        }
        __syncthreads();
    }

    if (lane < 2) g_x[r0 + lane] = x_reg;
}

// ---------------- 3) SVT: one-sided Jacobi, octet-parallel, incremental indices -------
// p/q advance by +1 (wrap 63->1) per round for fixed pid -> no modulo on the critical
// path; loads issue immediately at barrier release. One-division branchless rotation.
// V eliminated: Ltmp = C diag((s-tau)/s^3) (C^T M).
#define CSTR 68   // column stride in floats (float4-aligned)
__global__ void __launch_bounds__(1024) svt_kernel(
    const float* __restrict__ thP, const float* __restrict__ vp,
    const float* __restrict__ netap, float* __restrict__ out)
{
    __shared__ float Cs[64 * CSTR];
    __shared__ float Ms[64 * 65];
    __shared__ float Tt[64 * 65];
    __shared__ float nrm[64], coef[64];
    __shared__ float smax_s;
    int t = threadIdx.x, warp = t >> 5, lane = t & 31;
    int oct = lane >> 3, ol = lane & 7;

    for (int i = t; i < 4096; i += 1024) {
        int r = i >> 6, u = i & 63;
        float m = g_x[i] + thP[i];
        Ms[r * 65 + u] = m;
        Cs[u * CSTR + r] = m;
    }
    __syncthreads();
    if (t < 64) {
        float s2 = 0.f;
        #pragma unroll 8
        for (int r = 0; r < 64; r++) { float c = Cs[t * CSTR + r]; s2 += c * c; }
        nrm[t] = s2;
    }
    __syncthreads();

    if (t < 256) {
        int pid = warp * 4 + oct;   // pair id 0..31
        for (int sw = 0; sw < SWEEPS; sw++) {
            // tournament init for this sweep (matches 1+((pid-1+rr)%63) at rr=0)
            int p = (pid == 0) ? 0 : pid;
            int q = (pid == 0) ? 63 : 63 - pid;
            for (int rr = 0; rr < 63; rr++) {
                float4* cp4 = (float4*)(Cs + p * CSTR) + ol;
                float4* cq4 = (float4*)(Cs + q * CSTR) + ol;
                float4 p0 = cp4[0], p1 = cp4[8];
                float4 q0 = cq4[0], q1 = cq4[8];
                float apq = p0.x * q0.x + p0.y * q0.y + p0.z * q0.z + p0.w * q0.w
                          + p1.x * q1.x + p1.y * q1.y + p1.z * q1.z + p1.w * q1.w;
                #pragma unroll
                for (int off = 4; off; off >>= 1)
                    apq += __shfl_xor_sync(0xffffffffu, apq, off);
                float app = nrm[p], aqq = nrm[q];
                bool ok = apq * apq > 1e-24f * (app * aqq);
                float zeta = 0.5f * (aqq - app);
                float rad = __fsqrt_rn(zeta * zeta + apq * apq);
                float tt = __fdividef(apq, fabsf(zeta) + rad);
                tt = (zeta < 0.f) ? -tt : tt;
                tt = ok ? tt : 0.f;
                float c_ = __frsqrt_rn(1.f + tt * tt);
                float s_ = tt * c_;
                float4 n0, n1, m0, m1;
                n0.x = c_ * p0.x - s_ * q0.x; n0.y = c_ * p0.y - s_ * q0.y;
                n0.z = c_ * p0.z - s_ * q0.z; n0.w = c_ * p0.w - s_ * q0.w;
                n1.x = c_ * p1.x - s_ * q1.x; n1.y = c_ * p1.y - s_ * q1.y;
                n1.z = c_ * p1.z - s_ * q1.z; n1.w = c_ * p1.w - s_ * q1.w;
                m0.x = s_ * p0.x + c_ * q0.x; m0.y = s_ * p0.y + c_ * q0.y;
                m0.z = s_ * p0.z + c_ * q0.z; m0.w = s_ * p0.w + c_ * q0.w;
                m1.x = s_ * p1.x + c_ * q1.x; m1.y = s_ * p1.y + c_ * q1.y;
                m1.z = s_ * p1.z + c_ * q1.z; m1.w = s_ * p1.w + c_ * q1.w;
                cp4[0] = n0; cp4[8] = n1;
                cq4[0] = m0; cq4[8] = m1;
                if (ol == 0) {
                    nrm[p] = app - tt * apq;
                    nrm[q] = aqq + tt * apq;
                }
                // incremental tournament advance (no modulo)
                p = (pid == 0) ? 0 : ((p == 63) ? 1 : p + 1);
                q = (q == 63) ? 1 : q + 1;
                asm volatile("bar.sync 1, 256;" ::: "memory");
            }
        }
    }
    __syncthreads();

    if (t < 64) {
        float s2 = 0.f;
        #pragma unroll 8
        for (int r = 0; r < 64; r++) { float c = Cs[t * CSTR + r]; s2 += c * c; }
        nrm[t] = s2;
    }
    __syncthreads();
    if (t < 32) {
        float m = fmaxf(nrm[t], nrm[t + 32]);
        #pragma unroll
        for (int off = 16; off; off >>= 1) m = fmaxf(m, __shfl_xor_sync(0xffffffffu, m, off));
        if (t == 0) smax_s = sqrtf(m);
    }
    __syncthreads();
    float sig = 1.f / (1.f + expf(-(*vp)));
    float tau = sig * 0.4f * smax_s;
    if (t < 64) {
        float s2 = nrm[t];
        float si = sqrtf(s2);
        coef[t] = (si > tau) ? (si - tau) / (si * s2) : 0.f;
    }
    __syncthreads();

    #pragma unroll
    for (int s4 = 0; s4 < 4; s4++) {
        int e = t + 1024 * s4;
        int c = e >> 6, u = e & 63;
        float acc = 0.f;
        #pragma unroll 8
        for (int r = 0; r < 64; r++) acc += Cs[c * CSTR + r] * Ms[r * 65 + u];
        Tt[c * 65 + u] = coef[c] * acc;
    }
    __syncthreads();
    float neta = *netap;
    #pragma unroll
    for (int s4 = 0; s4 < 4; s4++) {
        int e = t + 1024 * s4;
        int r = e >> 6, u = e & 63;
        float acc = 0.f;
        #pragma unroll 8
        for (int c = 0; c < 64; c++) acc += Cs[c * CSTR + r] * Tt[c * 65 + u];
        out[e] = acc;
        out[NN + e] = thP[e] + neta * (g_x[e] - acc);
    }
}

// ---------------- launch ----------------
extern "C" void kernel_launch(void* const* d_in, const int* in_sizes, int n_in,
                              void* d_out, int out_size) {
    const float* inp  = (const float*)d_in[0];
    const float* L    = (const float*)d_in[1];
    const void*  mask = (const void*)d_in[2];
    const float* D    = (const float*)d_in[3];
    const float* thP  = (const float*)d_in[4];
    const float* v    = (const float*)d_in[5];
    const float* neta = (const float*)d_in[6];
    const float* l1   = (const float*)d_in[7];
    const float* l2   = (const float*)d_in[8];
    const float* rho  = (const float*)d_in[9];
    const float* S    = (const float*)d_in[10];

    cudaFuncSetAttribute(cg_kernel, cudaFuncAttributeMaxDynamicSharedMemorySize, SMEM_CG);

    convert_kernel<<<2048, 256>>>(D, l1, inp, L, mask, thP, l2, rho, S);
    cg_kernel<<<MV_BLOCKS, MV_TPB, SMEM_CG>>>();
    svt_kernel<<<1, 1024>>>(thP, v, neta, (float*)d_out);
}

// round 13
// speedup vs baseline: 1.0627x; 1.0627x over previous
#include <cuda_runtime.h>
#include <cuda_bf16.h>
#include <cuda_pipeline.h>

#define NN 4096
#define ITERS 8
#define SWEEPS 6
#define MV_BLOCKS 128
#define MV_TPB 512
#define NCHUNK 16
#define ROW_CB 512                      // bytes per row per chunk (256 bf16)
#define CHUNK_B (32 * ROW_CB)           // 16 KB per chunk stage

// dynamic smem layout for cg_kernel
#define OFF_ZS    0
#define OFF_RS    16384
#define OFF_APS   32768
#define OFF_MINV  49152
#define OFF_TSS   65536          // 64*33 floats = 8448 B
#define OFF_WRED  73984          // 16*3 floats = 192 B
#define OFF_SCL   74176          // 3 floats + pad -> 74240
#define OFF_STAGE 74240          // 3 x 16 KB
#define SMEM_CG   (OFF_STAGE + 3 * CHUNK_B)   // 123392 bytes

// ---------------- persistent device scratch (static, no runtime alloc) ----------------
__device__ __nv_bfloat16 g_D16[(size_t)NN * NN];   // lamda1 * D_tilda in bf16 (33.5 MB)
__device__ float g_qr[NN];        // q + rho
__device__ float g_Minv[NN];      // Jacobi preconditioner
__device__ float g_StS[64 * 64];  // lamda2 * S^T S
__device__ float g_x[NN], g_r[NN], g_z[NN], g_Az[NN];
__device__ int   g_barA[ITERS];

// ---------------- 0) convert: g_D16 = bf16(lamda1 * D)  (pure streaming, no smem) ----
__global__ void __launch_bounds__(256) convert_kernel(
    const float* __restrict__ D, const float* __restrict__ l1p)
{
    float l1 = *l1p;
    size_t base = ((size_t)blockIdx.x * 256 + threadIdx.x) * 8;   // float4 index
    const float4* src = (const float4*)D;
    __nv_bfloat162* dst = (__nv_bfloat162*)g_D16;
    float4 v[8];
    #pragma unroll
    for (int i = 0; i < 8; i++) v[i] = src[base + i];
    #pragma unroll
    for (int i = 0; i < 8; i++) {
        __nv_bfloat162 lo, hi;
        lo.x = __float2bfloat16_rn(v[i].x * l1); lo.y = __float2bfloat16_rn(v[i].y * l1);
        hi.x = __float2bfloat16_rn(v[i].z * l1); hi.y = __float2bfloat16_rn(v[i].w * l1);
        dst[(base + i) * 2]     = lo;
        dst[(base + i) * 2 + 1] = hi;
    }
}

// ---------------- 1) setup: StS, b, Minv, CG state, zero barriers --------------------
__global__ void __launch_bounds__(1024) setup_kernel(
    const float* __restrict__ inp, const float* __restrict__ L,
    const void* __restrict__ maskv, const float* __restrict__ thP,
    const float* __restrict__ D,
    const float* __restrict__ l1p, const float* __restrict__ l2p,
    const float* __restrict__ rhop, const float* __restrict__ S)
{
    __shared__ float Ss[64 * 65];
    __shared__ float Ts[64 * 65];
    int t = threadIdx.x;
    float l1 = *l1p, l2 = *l2p, rho = *rhop;

    // detect mask storage: 4-byte words (int32 0/1 or float 0.0/1.0) vs packed bytes
    const unsigned* maskw = (const unsigned*)maskv;
    unsigned wvd = maskw[t];
    int bad = (wvd != 0u && wvd != 1u && wvd != 0x3F800000u) ? 1 : 0;
    int bytemode = __syncthreads_or(bad);

    for (int i = t; i < 4096; i += 1024) {
        int h = i >> 6, a = i & 63;
        Ss[h * 65 + a] = S[i];
    }
    __syncthreads();
    for (int e = t; e < 4096; e += 1024) {
        int a = e >> 6, b = e & 63;
        float acc = 0.f;
        #pragma unroll 8
        for (int h = 0; h < 64; h++) acc += Ss[h * 65 + a] * Ss[h * 65 + b];
        acc *= l2;
        Ts[a * 65 + b] = acc;
        g_StS[e] = acc;
    }
    __syncthreads();
    const unsigned char* maskb = (const unsigned char*)maskv;
    for (int n = t; n < NN; n += 1024) {
        float qf;
        if (bytemode) qf = (maskb[n] != 0) ? 1.f : 0.f;
        else          qf = (maskw[n] != 0u) ? 1.f : 0.f;
        float qr = qf + rho;
        g_qr[n] = qr;
        int c = n & 63;
        float dg = D[(size_t)n * (NN + 1)];
        float denom = qr + l1 * dg + Ts[c * 65 + c];
        float minv = 1.f / denom;
        g_Minv[n] = minv;
        float bb = rho * (L[n] - thP[n]) + (qf != 0.f ? inp[n] : 0.f);
        g_r[n] = bb;
        g_z[n] = minv * bb;
    }
    if (t < ITERS) g_barA[t] = 0;
}

// ---------------- 2) PERSISTENT CG: one grid barrier per iteration -------------------
// Each block publishes its 32 Az values, then redundantly maintains the FULL r/z/Ap
// vectors in its own smem (identical op order in every block -> bitwise-identical
// alpha/beta everywhere; no global dot reduction, no atomics).
__global__ void __launch_bounds__(MV_TPB) cg_kernel()
{
    extern __shared__ __align__(16) char sm[];
    float* zs    = (float*)(sm + OFF_ZS);
    float* rs    = (float*)(sm + OFF_RS);
    float* Aps   = (float*)(sm + OFF_APS);
    float* Minvs = (float*)(sm + OFF_MINV);
    float* Tss   = (float*)(sm + OFF_TSS);
    float* wred  = (float*)(sm + OFF_WRED);
    float* scl   = (float*)(sm + OFF_SCL);
    __nv_bfloat16* stage = (__nv_bfloat16*)(sm + OFF_STAGE);

    int t = threadIdx.x, b = blockIdx.x;
    int row0 = b * 32;
    int h = row0 >> 6;
    int u0 = (b & 1) * 32;
    int warp = t >> 5, lane = t & 31;
    int r0 = row0 + 2 * warp;

    // init local full vectors + StS tile
    for (int i = t; i < NN; i += MV_TPB) {
        zs[i]  = __ldcg(&g_z[i]);
        rs[i]  = __ldcg(&g_r[i]);
        Minvs[i] = __ldcg(&g_Minv[i]);
        Aps[i] = 0.f;
    }
    for (int i = t; i < 64 * 32; i += MV_TPB) {
        int bb = i >> 5, uu = i & 31;
        Tss[bb * 33 + uu] = g_StS[bb * 64 + u0 + uu];
    }

    int lrow = t >> 4;
    int loff = (t & 15) * 32;
    const char* srow = (const char*)(g_D16 + (size_t)(row0 + lrow) * NN);

    float rz_prev = 0.f, pAp_prev = 0.f;
    float zr_save = 0.f, p_reg = 0.f, x_reg = 0.f;   // meaningful for lane<2 threads

    for (int k = 0; k < ITERS; k++) {
        // ---- matvec on local zs ----
        #pragma unroll
        for (int c = 0; c < 2; c++) {
            char* d = (char*)stage + (c % 3) * CHUNK_B + lrow * ROW_CB + loff;
            const char* s = srow + c * ROW_CB + loff;
            __pipeline_memcpy_async(d, s, 16);
            __pipeline_memcpy_async(d + 16, s + 16, 16);
            __pipeline_commit();
        }
        __syncthreads();   // zs/Aps/etc ready (also covers init on k=0)

        float acc0 = 0.f, acc1 = 0.f;
        #pragma unroll
        for (int c = 0; c < NCHUNK; c++) {
            if (c < NCHUNK - 1) __pipeline_wait_prior(1);
            else                __pipeline_wait_prior(0);
            __syncthreads();
            const char* st = (const char*)stage + (c % 3) * CHUNK_B;
            uint4 d0 = *(const uint4*)(st + (2 * warp) * ROW_CB + lane * 16);
            uint4 d1 = *(const uint4*)(st + (2 * warp + 1) * ROW_CB + lane * 16);
            float4 za = *(const float4*)(zs + c * 256 + lane * 8);
            float4 zb = *(const float4*)(zs + c * 256 + lane * 8 + 4);
            float2 p0 = __bfloat1622float2(*(__nv_bfloat162*)&d0.x);
            float2 p1 = __bfloat1622float2(*(__nv_bfloat162*)&d0.y);
            float2 p2 = __bfloat1622float2(*(__nv_bfloat162*)&d0.z);
            float2 p3 = __bfloat1622float2(*(__nv_bfloat162*)&d0.w);
            acc0 += p0.x * za.x + p0.y * za.y + p1.x * za.z + p1.y * za.w
                  + p2.x * zb.x + p2.y * zb.y + p3.x * zb.z + p3.y * zb.w;
            p0 = __bfloat1622float2(*(__nv_bfloat162*)&d1.x);
            p1 = __bfloat1622float2(*(__nv_bfloat162*)&d1.y);
            p2 = __bfloat1622float2(*(__nv_bfloat162*)&d1.z);
            p3 = __bfloat1622float2(*(__nv_bfloat162*)&d1.w);
            acc1 += p0.x * za.x + p0.y * za.y + p1.x * za.z + p1.y * za.w
                  + p2.x * zb.x + p2.y * zb.y + p3.x * zb.z + p3.y * zb.w;
            if (c + 2 < NCHUNK) {
                int cc = c + 2;
                char* d = (char*)stage + (cc % 3) * CHUNK_B + lrow * ROW_CB + loff;
                const char* s = srow + cc * ROW_CB + loff;
                __pipeline_memcpy_async(d, s, 16);
                __pipeline_memcpy_async(d + 16, s + 16, 16);
                __pipeline_commit();
            }
        }

        // lamda2 * (Z @ StS) term
        {
            int uu0 = (r0 & 63) - u0;
            int uu1 = uu0 + 1;
            float zl  = zs[(h << 6) + lane];
            float zh2 = zs[(h << 6) + lane + 32];
            acc0 += Tss[lane * 33 + uu0] * zl + Tss[(lane + 32) * 33 + uu0] * zh2;
            acc1 += Tss[lane * 33 + uu1] * zl + Tss[(lane + 32) * 33 + uu1] * zh2;
        }
        #pragma unroll
        for (int off = 16; off; off >>= 1) {
            acc0 += __shfl_xor_sync(0xffffffffu, acc0, off);
            acc1 += __shfl_xor_sync(0xffffffffu, acc1, off);
        }
        if (lane < 2) {
            int row = r0 + lane;
            float a = lane ? acc1 : acc0;
            zr_save = zs[row];
            float Azv = a + g_qr[row] * zr_save;
            g_Az[row] = Azv;          // publish own 32 Az values
            __threadfence();
        }
        __syncthreads();

        // ---- single grid barrier ----
        if (t == 0) {
            atomicAdd(&g_barA[k], 1);
            while (*(volatile int*)&g_barA[k] < MV_BLOCKS) __nanosleep(32);
        }
        __syncthreads();

        // ---- read full Az; local dots (identical in every block) ----
        float4 aza = __ldcg((const float4*)g_Az + 2 * t);
        float4 azb = __ldcg((const float4*)g_Az + 2 * t + 1);
        float az[8] = {aza.x, aza.y, aza.z, aza.w, azb.x, azb.y, azb.z, azb.w};
        float dzAz = 0.f, dzAp = 0.f, drz = 0.f;
        #pragma unroll
        for (int i = 0; i < 8; i++) {
            int n = t * 8 + i;
            float zn = zs[n];
            dzAz += zn * az[i];
            dzAp += zn * Aps[n];
            drz  += rs[n] * zn;
        }
        #pragma unroll
        for (int off = 16; off; off >>= 1) {
            dzAz += __shfl_xor_sync(0xffffffffu, dzAz, off);
            dzAp += __shfl_xor_sync(0xffffffffu, dzAp, off);
            drz  += __shfl_xor_sync(0xffffffffu, drz,  off);
        }
        if (lane == 0) {
            wred[warp * 3 + 0] = dzAz;
            wred[warp * 3 + 1] = dzAp;
            wred[warp * 3 + 2] = drz;
        }
        __syncthreads();
        if (warp == 0) {
            float a = (lane < 16) ? wred[lane * 3 + 0] : 0.f;
            float bq = (lane < 16) ? wred[lane * 3 + 1] : 0.f;
            float cc = (lane < 16) ? wred[lane * 3 + 2] : 0.f;
            #pragma unroll
            for (int off = 8; off; off >>= 1) {
                a  += __shfl_xor_sync(0xffffffffu, a,  off);
                bq += __shfl_xor_sync(0xffffffffu, bq, off);
                cc += __shfl_xor_sync(0xffffffffu, cc, off);
            }
            if (lane == 0) { scl[0] = a; scl[1] = bq; scl[2] = cc; }
        }
        __syncthreads();
        float zAz = scl[0], zAp = scl[1], rz = scl[2];
        float beta = (k > 0 && rz_prev != 0.f) ? rz / rz_prev : 0.f;
        float pAp = zAz + 2.f * beta * zAp + beta * beta * pAp_prev;
        float alpha = (pAp != 0.f) ? rz / pAp : 0.f;
        rz_prev = rz; pAp_prev = pAp;

        // own-row p/x (zr_save is z_k for this row, captured pre-update)
        if (lane < 2) {
            p_reg = zr_save + beta * p_reg;
            x_reg = x_reg + alpha * p_reg;
        }

        // ---- redundant full-vector update (8 rows/thread) ----
        #pragma unroll
        for (int i = 0; i < 8; i++) {
            int n = t * 8 + i;
            float Apn = az[i] + beta * Aps[n];
            Aps[n] = Apn;
            float rn = rs[n] - alpha * Apn;
            rs[n] = rn;
            zs[n] = Minvs[n] * rn;
        }
        __syncthreads();
    }

    if (lane < 2) g_x[r0 + lane] = x_reg;
}

// ---------------- 3) SVT: one-sided Jacobi, octet-parallel, incremental indices -------
// p/q advance by +1 (wrap 63->1) per round for fixed pid -> no modulo on the critical
// path; loads issue immediately at barrier release. One-division branchless rotation.
// V eliminated: Ltmp = C diag((s-tau)/s^3) (C^T M).
#define CSTR 68   // column stride in floats (float4-aligned)
__global__ void __launch_bounds__(1024) svt_kernel(
    const float* __restrict__ thP, const float* __restrict__ vp,
    const float* __restrict__ netap, float* __restrict__ out)
{
    __shared__ float Cs[64 * CSTR];
    __shared__ float Ms[64 * 65];
    __shared__ float Tt[64 * 65];
    __shared__ float nrm[64], coef[64];
    __shared__ float smax_s;
    int t = threadIdx.x, warp = t >> 5, lane = t & 31;
    int oct = lane >> 3, ol = lane & 7;

    for (int i = t; i < 4096; i += 1024) {
        int r = i >> 6, u = i & 63;
        float m = g_x[i] + thP[i];
        Ms[r * 65 + u] = m;
        Cs[u * CSTR + r] = m;
    }
    __syncthreads();
    if (t < 64) {
        float s2 = 0.f;
        #pragma unroll 8
        for (int r = 0; r < 64; r++) { float c = Cs[t * CSTR + r]; s2 += c * c; }
        nrm[t] = s2;
    }
    __syncthreads();

    if (t < 256) {
        int pid = warp * 4 + oct;   // pair id 0..31
        for (int sw = 0; sw < SWEEPS; sw++) {
            // tournament init for this sweep (matches 1+((pid-1+rr)%63) at rr=0)
            int p = (pid == 0) ? 0 : pid;
            int q = (pid == 0) ? 63 : 63 - pid;
            for (int rr = 0; rr < 63; rr++) {
                float4* cp4 = (float4*)(Cs + p * CSTR) + ol;
                float4* cq4 = (float4*)(Cs + q * CSTR) + ol;
                float4 p0 = cp4[0], p1 = cp4[8];
                float4 q0 = cq4[0], q1 = cq4[8];
                float apq = p0.x * q0.x + p0.y * q0.y + p0.z * q0.z + p0.w * q0.w
                          + p1.x * q1.x + p1.y * q1.y + p1.z * q1.z + p1.w * q1.w;
                #pragma unroll
                for (int off = 4; off; off >>= 1)
                    apq += __shfl_xor_sync(0xffffffffu, apq, off);
                float app = nrm[p], aqq = nrm[q];
                bool ok = apq * apq > 1e-24f * (app * aqq);
                float zeta = 0.5f * (aqq - app);
                float rad = __fsqrt_rn(zeta * zeta + apq * apq);
                float tt = __fdividef(apq, fabsf(zeta) + rad);
                tt = (zeta < 0.f) ? -tt : tt;
                tt = ok ? tt : 0.f;
                float c_ = __frsqrt_rn(1.f + tt * tt);
                float s_ = tt * c_;
                float4 n0, n1, m0, m1;
                n0.x = c_ * p0.x - s_ * q0.x; n0.y = c_ * p0.y - s_ * q0.y;
                n0.z = c_ * p0.z - s_ * q0.z; n0.w = c_ * p0.w - s_ * q0.w;
                n1.x = c_ * p1.x - s_ * q1.x; n1.y = c_ * p1.y - s_ * q1.y;
                n1.z = c_ * p1.z - s_ * q1.z; n1.w = c_ * p1.w - s_ * q1.w;
                m0.x = s_ * p0.x + c_ * q0.x; m0.y = s_ * p0.y + c_ * q0.y;
                m0.z = s_ * p0.z + c_ * q0.z; m0.w = s_ * p0.w + c_ * q0.w;
                m1.x = s_ * p1.x + c_ * q1.x; m1.y = s_ * p1.y + c_ * q1.y;
                m1.z = s_ * p1.z + c_ * q1.z; m1.w = s_ * p1.w + c_ * q1.w;
                cp4[0] = n0; cp4[8] = n1;
                cq4[0] = m0; cq4[8] = m1;
                if (ol == 0) {
                    nrm[p] = app - tt * apq;
                    nrm[q] = aqq + tt * apq;
                }
                // incremental tournament advance (no modulo)
                p = (pid == 0) ? 0 : ((p == 63) ? 1 : p + 1);
                q = (q == 63) ? 1 : q + 1;
                asm volatile("bar.sync 1, 256;" ::: "memory");
            }
        }
    }
    __syncthreads();

    if (t < 64) {
        float s2 = 0.f;
        #pragma unroll 8
        for (int r = 0; r < 64; r++) { float c = Cs[t * CSTR + r]; s2 += c * c; }
        nrm[t] = s2;
    }
    __syncthreads();
    if (t < 32) {
        float m = fmaxf(nrm[t], nrm[t + 32]);
        #pragma unroll
        for (int off = 16; off; off >>= 1) m = fmaxf(m, __shfl_xor_sync(0xffffffffu, m, off));
        if (t == 0) smax_s = sqrtf(m);
    }
    __syncthreads();
    float sig = 1.f / (1.f + expf(-(*vp)));
    float tau = sig * 0.4f * smax_s;
    if (t < 64) {
        float s2 = nrm[t];
        float si = sqrtf(s2);
        coef[t] = (si > tau) ? (si - tau) / (si * s2) : 0.f;
    }
    __syncthreads();

    #pragma unroll
    for (int s4 = 0; s4 < 4; s4++) {
        int e = t + 1024 * s4;
        int c = e >> 6, u = e & 63;
        float acc = 0.f;
        #pragma unroll 8
        for (int r = 0; r < 64; r++) acc += Cs[c * CSTR + r] * Ms[r * 65 + u];
        Tt[c * 65 + u] = coef[c] * acc;
    }
    __syncthreads();
    float neta = *netap;
    #pragma unroll
    for (int s4 = 0; s4 < 4; s4++) {
        int e = t + 1024 * s4;
        int r = e >> 6, u = e & 63;
        float acc = 0.f;
        #pragma unroll 8
        for (int c = 0; c < 64; c++) acc += Cs[c * CSTR + r] * Tt[c * 65 + u];
        out[e] = acc;
        out[NN + e] = thP[e] + neta * (g_x[e] - acc);
    }
}

// ---------------- launch ----------------
extern "C" void kernel_launch(void* const* d_in, const int* in_sizes, int n_in,
                              void* d_out, int out_size) {
    const float* inp  = (const float*)d_in[0];
    const float* L    = (const float*)d_in[1];
    const void*  mask = (const void*)d_in[2];
    const float* D    = (const float*)d_in[3];
    const float* thP  = (const float*)d_in[4];
    const float* v    = (const float*)d_in[5];
    const float* neta = (const float*)d_in[6];
    const float* l1   = (const float*)d_in[7];
    const float* l2   = (const float*)d_in[8];
    const float* rho  = (const float*)d_in[9];
    const float* S    = (const float*)d_in[10];

    cudaFuncSetAttribute(cg_kernel, cudaFuncAttributeMaxDynamicSharedMemorySize, SMEM_CG);

    convert_kernel<<<2048, 256>>>(D, l1);
    setup_kernel<<<1, 1024>>>(inp, L, mask, thP, D, l1, l2, rho, S);
    cg_kernel<<<MV_BLOCKS, MV_TPB, SMEM_CG>>>();
    svt_kernel<<<1, 1024>>>(thP, v, neta, (float*)d_out);
}